// round 1
// baseline (speedup 1.0000x reference)
#include <cuda_runtime.h>

#define NCLS 4
#define VMX 64
#define NF 28     // input features
#define HID 64
#define NGATE 256 // 4*HID
#define OUTF 768
#define NBINS (NCLS*VMX*NF)   // 7168
#define RB 32     // rows per block in main kernel

// scratch (no allocations allowed)
__device__ int   g_counts[NBINS];
__device__ int   g_class[NCLS];
__device__ float g_prob[NBINS];

__global__ void zero_kernel() {
    int i = blockIdx.x * blockDim.x + threadIdx.x;
    if (i < NBINS) g_counts[i] = 0;
    if (i < NCLS)  g_class[i] = 0;
}

__global__ void hist_kernel(const float* __restrict__ VS,
                            const int* __restrict__ Level, int N) {
    __shared__ int s_counts[NBINS];
    __shared__ int s_cls[NCLS];
    for (int i = threadIdx.x; i < NBINS; i += blockDim.x) s_counts[i] = 0;
    if (threadIdx.x < NCLS) s_cls[threadIdx.x] = 0;
    __syncthreads();
    int stride = gridDim.x * blockDim.x;
    for (int r = blockIdx.x * blockDim.x + threadIdx.x; r < N; r += stride) {
        int lev = Level[r];
        atomicAdd(&s_cls[lev], 1);
        int base = lev * VMX;
#pragma unroll
        for (int c = 0; c < NF; c++) {
            int v = (int)VS[(size_t)r * NF + c];
            atomicAdd(&s_counts[(base + v) * NF + c], 1);
        }
    }
    __syncthreads();
    for (int i = threadIdx.x; i < NBINS; i += blockDim.x)
        if (s_counts[i]) atomicAdd(&g_counts[i], s_counts[i]);
    if (threadIdx.x < NCLS && s_cls[threadIdx.x])
        atomicAdd(&g_class[threadIdx.x], s_cls[threadIdx.x]);
}

__global__ void prob_kernel() {
    int i = blockIdx.x * blockDim.x + threadIdx.x;
    if (i < NBINS) {
        int cls = i / (VMX * NF);
        g_prob[i] = (float)g_counts[i] / (float)g_class[cls];
    }
}

__device__ __forceinline__ float sigmoidf_(float x) {
    return 1.0f / (1.0f + __expf(-x));
}

// Fused: casual-weight -> gates -> activations -> h @ W_fc^T + b_fc,
// plus CC row copy (overlaps the memory-bound copy with FMA-bound GEMM).
__global__ __launch_bounds__(256)
void main_kernel(const float* __restrict__ VS,
                 const int* __restrict__ Level,
                 const float* __restrict__ CC,
                 const float* __restrict__ W_ih,
                 const float* __restrict__ b_ih,
                 const float* __restrict__ b_hh,
                 const float* __restrict__ W_fc,
                 const float* __restrict__ b_fc,
                 float* __restrict__ cc_out,
                 float* __restrict__ vs_out,
                 int N)
{
    __shared__ float x_s[RB][NF];
    __shared__ float h_s[RB][HID + 1];
    __shared__ int   lev_s[RB];
    __shared__ float4 w4[HID * 32];        // 32 KB, also reused as gates buffer
    float* shbuf = (float*)w4;             // gates: [RB][NGATE] = 8192 floats

    const int t = threadIdx.x;
    const int row0 = blockIdx.x * RB;

    // ---- CC copy for this block's rows (float4, coalesced) ----
    {
        const float4* src = (const float4*)(CC + (size_t)row0 * OUTF);
        float4* dst = (float4*)(cc_out + (size_t)row0 * OUTF);
        int nvec;
        if (row0 + RB <= N) nvec = RB * OUTF / 4;
        else nvec = (N > row0 ? (N - row0) * OUTF / 4 : 0);
        for (int i = t; i < nvec; i += 256) dst[i] = src[i];
    }

    if (t < RB) {
        int r = row0 + t;
        lev_s[t] = (r < N) ? Level[r] : 0;
    }
    __syncthreads();

    // ---- stage A: x = VS * prob ----
    for (int i = t; i < RB * NF; i += 256) {
        int r = i / NF, c = i % NF;
        float xv = 0.0f;
        if (row0 + r < N) {
            float v = VS[(size_t)(row0 + r) * NF + c];
            int lev = lev_s[r];
            xv = v * g_prob[(lev * VMX + (int)v) * NF + c];
        }
        x_s[r][c] = xv;
    }
    __syncthreads();

    // ---- stage B: gates; thread t owns gate column t ----
    {
        float w[NF];
#pragma unroll
        for (int k = 0; k < NF; k++) w[k] = W_ih[t * NF + k];
        float b = b_ih[t] + b_hh[t];
#pragma unroll 4
        for (int r = 0; r < RB; r++) {
            float acc = b;
#pragma unroll
            for (int k = 0; k < NF; k++) acc += w[k] * x_s[r][k];
            shbuf[r * NGATE + t] = acc;
        }
    }
    __syncthreads();

    // ---- stage C: activations -> h (f gate unused since c0 = 0) ----
    {
        int u = t & 63, rg = t >> 6;
#pragma unroll
        for (int r = rg; r < RB; r += 4) {
            float gi = shbuf[r * NGATE + u];
            float gg = shbuf[r * NGATE + 128 + u];
            float go = shbuf[r * NGATE + 192 + u];
            float c = sigmoidf_(gi) * tanhf(gg);
            float h = sigmoidf_(go) * tanhf(c);
            h_s[r][u] = h;
        }
    }

    // ---- stage D: out = h @ W_fc^T + b_fc ; 6 col-tiles of 128 ----
    const int tc = t & 31;   // col group (4 cols each)
    const int tr = t >> 5;   // row group (4 rows each), 0..7
#pragma unroll 1
    for (int ct = 0; ct < 6; ct++) {
        __syncthreads();   // protect shbuf/w4 from previous use
        // load W tile: w4[k*32 + cg] = cols (ct*128+cg*4 .. +3) at depth k
        for (int i = t; i < HID * 32; i += 256) {
            int k = i & 63, cg = i >> 6;
            int colbase = (ct * 128 + cg * 4) * HID + k;
            float4 w;
            w.x = W_fc[colbase];
            w.y = W_fc[colbase + HID];
            w.z = W_fc[colbase + 2 * HID];
            w.w = W_fc[colbase + 3 * HID];
            w4[k * 32 + cg] = w;
        }
        __syncthreads();

        float acc0x = 0, acc0y = 0, acc0z = 0, acc0w = 0;
        float acc1x = 0, acc1y = 0, acc1z = 0, acc1w = 0;
        float acc2x = 0, acc2y = 0, acc2z = 0, acc2w = 0;
        float acc3x = 0, acc3y = 0, acc3z = 0, acc3w = 0;
#pragma unroll 8
        for (int k = 0; k < HID; k++) {
            float4 wv = w4[k * 32 + tc];
            float h0 = h_s[tr * 4 + 0][k];
            float h1 = h_s[tr * 4 + 1][k];
            float h2 = h_s[tr * 4 + 2][k];
            float h3 = h_s[tr * 4 + 3][k];
            acc0x += h0 * wv.x; acc0y += h0 * wv.y; acc0z += h0 * wv.z; acc0w += h0 * wv.w;
            acc1x += h1 * wv.x; acc1y += h1 * wv.y; acc1z += h1 * wv.z; acc1w += h1 * wv.w;
            acc2x += h2 * wv.x; acc2y += h2 * wv.y; acc2z += h2 * wv.z; acc2w += h2 * wv.w;
            acc3x += h3 * wv.x; acc3y += h3 * wv.y; acc3z += h3 * wv.z; acc3w += h3 * wv.w;
        }
        float4 bb = ((const float4*)b_fc)[ct * 32 + tc];
        int colbase = ct * 128 + tc * 4;
#pragma unroll
        for (int i = 0; i < 4; i++) {
            int row = row0 + tr * 4 + i;
            if (row < N) {
                float4 o;
                float ax = (i == 0) ? acc0x : (i == 1) ? acc1x : (i == 2) ? acc2x : acc3x;
                float ay = (i == 0) ? acc0y : (i == 1) ? acc1y : (i == 2) ? acc2y : acc3y;
                float az = (i == 0) ? acc0z : (i == 1) ? acc1z : (i == 2) ? acc2z : acc3z;
                float aw = (i == 0) ? acc0w : (i == 1) ? acc1w : (i == 2) ? acc2w : acc3w;
                o.x = ax + bb.x; o.y = ay + bb.y; o.z = az + bb.z; o.w = aw + bb.w;
                *(float4*)(vs_out + (size_t)row * OUTF + colbase) = o;
            }
        }
    }
}

__global__ void tail_kernel(const int* __restrict__ Level,
                            const int* __restrict__ Depart,
                            float* __restrict__ lev_out,
                            float* __restrict__ dep_out, int N) {
    int i = blockIdx.x * blockDim.x + threadIdx.x;
    if (i < N) {
        lev_out[i] = (float)Level[i];
        dep_out[i] = (float)Depart[i];
    }
}

extern "C" void kernel_launch(void* const* d_in, const int* in_sizes, int n_in,
                              void* d_out, int out_size) {
    const float* VS     = (const float*)d_in[0];
    const float* CC     = (const float*)d_in[1];
    const int*   Level  = (const int*)d_in[2];
    const int*   Depart = (const int*)d_in[3];
    const float* W_ih   = (const float*)d_in[4];
    // d_in[5] = W_hh, unused (h0 = 0)
    const float* b_ih   = (const float*)d_in[6];
    const float* b_hh   = (const float*)d_in[7];
    const float* W_fc   = (const float*)d_in[8];
    const float* b_fc   = (const float*)d_in[9];

    int N = in_sizes[0] / NF;

    float* out = (float*)d_out;
    float* cc_out  = out;
    float* vs_out  = out + (size_t)N * OUTF;
    float* lev_out = out + (size_t)2 * N * OUTF;
    float* dep_out = lev_out + N;

    zero_kernel<<<(NBINS + 255) / 256, 256>>>();
    hist_kernel<<<256, 256>>>(VS, Level, N);
    prob_kernel<<<(NBINS + 255) / 256, 256>>>();
    main_kernel<<<(N + RB - 1) / RB, 256>>>(VS, Level, CC, W_ih, b_ih, b_hh,
                                            W_fc, b_fc, cc_out, vs_out, N);
    tail_kernel<<<(N + 255) / 256, 256>>>(Level, Depart, lev_out, dep_out, N);
}

// round 2
// speedup vs baseline: 1.0484x; 1.0484x over previous
#include <cuda_runtime.h>

#define NCLS 4
#define VMX 64
#define NF 28
#define HID 64
#define NGATE 256
#define OUTF 768
#define NBINS (NCLS*VMX*NF)   // 7168
#define RB 64                 // rows per block in main kernel

typedef unsigned long long ull;

// scratch (no allocations allowed)
__device__ int   g_counts[NBINS];
__device__ int   g_class[NCLS];
__device__ float g_prob[NBINS];

// ---------------- small prologue kernels ----------------
__global__ void zero_kernel() {
    int i = blockIdx.x * blockDim.x + threadIdx.x;
    if (i < NBINS) g_counts[i] = 0;
    if (i < NCLS)  g_class[i] = 0;
}

__global__ void hist_kernel(const float* __restrict__ VS,
                            const int* __restrict__ Level, int N) {
    __shared__ int s_counts[NBINS];
    __shared__ int s_cls[NCLS];
    for (int i = threadIdx.x; i < NBINS; i += blockDim.x) s_counts[i] = 0;
    if (threadIdx.x < NCLS) s_cls[threadIdx.x] = 0;
    __syncthreads();
    int stride = gridDim.x * blockDim.x;
    for (int r = blockIdx.x * blockDim.x + threadIdx.x; r < N; r += stride) {
        int lev = Level[r];
        atomicAdd(&s_cls[lev], 1);
        int base = lev * VMX;
#pragma unroll
        for (int c = 0; c < NF; c++) {
            int v = (int)VS[(size_t)r * NF + c];
            atomicAdd(&s_counts[(base + v) * NF + c], 1);
        }
    }
    __syncthreads();
    for (int i = threadIdx.x; i < NBINS; i += blockDim.x)
        if (s_counts[i]) atomicAdd(&g_counts[i], s_counts[i]);
    if (threadIdx.x < NCLS && s_cls[threadIdx.x])
        atomicAdd(&g_class[threadIdx.x], s_cls[threadIdx.x]);
}

__global__ void prob_kernel() {
    int i = blockIdx.x * blockDim.x + threadIdx.x;
    if (i < NBINS) {
        int cls = i / (VMX * NF);
        g_prob[i] = (float)g_counts[i] / (float)g_class[cls];
    }
}

// ---------------- helpers ----------------
__device__ __forceinline__ float sigmoidf_(float x) {
    return 1.0f / (1.0f + __expf(-x));
}
__device__ __forceinline__ ull dup2(float x) {
    ull p; asm("mov.b64 %0, {%1, %1};" : "=l"(p) : "f"(x)); return p;
}
__device__ __forceinline__ void ffma2(ull& d, ull a, ull b) {
    asm("fma.rn.f32x2 %0, %1, %2, %0;" : "+l"(d) : "l"(a), "l"(b));
}
__device__ __forceinline__ void ld2s(const float* p, ull& a, ull& b) {
    double2 d = *(const double2*)p;
    a = __double_as_longlong(d.x); b = __double_as_longlong(d.y);
}

// dynamic smem layout (bytes)
#define XD_OFF   0          // [64][28] ull   = 14336
#define WGA_OFF  14336      // [28][132] f    = 14784
#define WGB_OFF  29120      // [28][132] f    = 14784
#define GOUT_OFF 43904      // [64][256] f    = 65536  -> 109440
#define HD_OFF   0          // [64][64] ull   = 32768
#define WFA_OFF  32768      // [64][132] f    = 33792
#define WFB_OFF  66560      // [64][132] f    = 33792  -> 100352
#define SMEM_BYTES 109440

__global__ __launch_bounds__(256, 2)
void main_kernel(const float* __restrict__ VS,
                 const int* __restrict__ Level,
                 const int* __restrict__ Depart,
                 const float* __restrict__ CC,
                 const float* __restrict__ W_ih,
                 const float* __restrict__ b_ih,
                 const float* __restrict__ b_hh,
                 const float* __restrict__ W_fc,
                 const float* __restrict__ b_fc,
                 float* __restrict__ cc_out,
                 float* __restrict__ vs_out,
                 float* __restrict__ lev_out,
                 float* __restrict__ dep_out,
                 int N)
{
    extern __shared__ char sm[];
    __shared__ int lev_s[RB];

    const int t = threadIdx.x;
    const int row0 = blockIdx.x * RB;
    const int cg = t & 31;          // col group (8 cols)
    const int rg = t >> 5;          // row group (8 rows) == warp id
    const int r0 = rg * 8;
    const int c0 = cg * 8;

    // ---- Level/Depart tail + lev_s ----
    if (t < RB) {
        int r = row0 + t;
        int lv = (r < N) ? Level[r] : 0;
        lev_s[t] = lv;
        if (r < N) { lev_out[r] = (float)lv; dep_out[r] = (float)Depart[r]; }
    }

    // ---- load W_ih gate tiles into wgA/wgB (stride 132) ----
    {
        float* wgA = (float*)(sm + WGA_OFF);
        float* wgB = (float*)(sm + WGB_OFF);
        int c = t;  // 256 threads = 256 gate cols
        int ccg = c >> 3, j = c & 7;
        float* dst = (j < 4) ? wgA : wgB;
        int jj = j & 3;
#pragma unroll
        for (int k = 0; k < NF; k++)
            dst[k * 132 + ccg * 4 + jj] = W_ih[c * NF + k];
    }
    __syncthreads();

    // ---- x = VS * prob, duplicated f32x2, into xd ----
    {
        ull* xd = (ull*)(sm + XD_OFF);
        for (int i = t; i < RB * NF; i += 256) {
            int r = i / NF, c = i % NF;
            float xv = 0.0f;
            if (row0 + r < N) {
                float v = VS[(size_t)(row0 + r) * NF + c];
                int lev = lev_s[r];
                xv = v * g_prob[(lev * VMX + (int)v) * NF + c];
            }
            xd[r * NF + c] = dup2(xv);
        }
    }

    // ---- CC copy (overlaps with DRAM-idle compute phases globally) ----
    {
        const float4* src = (const float4*)(CC + (size_t)row0 * OUTF);
        float4* dst = (float4*)(cc_out + (size_t)row0 * OUTF);
        int nrow = (row0 + RB <= N) ? RB : (N > row0 ? N - row0 : 0);
        int nvec = nrow * OUTF / 4;
        for (int i = t; i < nvec; i += 256) dst[i] = src[i];
    }
    __syncthreads();

    // ---- gates GEMM: [64x28] @ [28x256], 8x8 f32x2 tiles ----
    {
        const ull* xd = (const ull*)(sm + XD_OFF);
        const float* wgA = (const float*)(sm + WGA_OFF);
        const float* wgB = (const float*)(sm + WGB_OFF);
        float* gout = (float*)(sm + GOUT_OFF);

        ull acc[8][4];
        {
            ull bA0, bA1, bB0, bB1;
            float bi[8];
#pragma unroll
            for (int j = 0; j < 8; j++) bi[j] = b_ih[c0 + j] + b_hh[c0 + j];
            bA0 = __double_as_longlong(__hiloint2double(__float_as_int(bi[1]), __float_as_int(bi[0])));
            bA1 = __double_as_longlong(__hiloint2double(__float_as_int(bi[3]), __float_as_int(bi[2])));
            bB0 = __double_as_longlong(__hiloint2double(__float_as_int(bi[5]), __float_as_int(bi[4])));
            bB1 = __double_as_longlong(__hiloint2double(__float_as_int(bi[7]), __float_as_int(bi[6])));
#pragma unroll
            for (int i = 0; i < 8; i++) {
                acc[i][0] = bA0; acc[i][1] = bA1; acc[i][2] = bB0; acc[i][3] = bB1;
            }
        }
#pragma unroll 4
        for (int k = 0; k < NF; k++) {
            ull w0, w1, w2, w3;
            ld2s(wgA + k * 132 + cg * 4, w0, w1);
            ld2s(wgB + k * 132 + cg * 4, w2, w3);
#pragma unroll
            for (int i = 0; i < 8; i++) {
                ull hv = xd[(r0 + i) * NF + k];
                ffma2(acc[i][0], hv, w0);
                ffma2(acc[i][1], hv, w1);
                ffma2(acc[i][2], hv, w2);
                ffma2(acc[i][3], hv, w3);
            }
        }
#pragma unroll
        for (int i = 0; i < 8; i++) {
            double2* dst = (double2*)(gout + (r0 + i) * NGATE + c0);
            dst[0] = make_double2(__longlong_as_double(acc[i][0]), __longlong_as_double(acc[i][1]));
            dst[1] = make_double2(__longlong_as_double(acc[i][2]), __longlong_as_double(acc[i][3]));
        }
    }
    __syncthreads();

    // ---- activations -> hd (duplicated f32x2) ----
    {
        const float* gout = (const float*)(sm + GOUT_OFF);
        ull* hd = (ull*)(sm + HD_OFF);
        int u = t & 63, rb = t >> 6;  // 4 row phases
#pragma unroll
        for (int m = 0; m < 16; m++) {
            int r = rb + 4 * m;
            float gi = gout[r * NGATE + u];
            float gg = gout[r * NGATE + 128 + u];
            float go = gout[r * NGATE + 192 + u];
            float c = sigmoidf_(gi) * tanhf(gg);
            float h = sigmoidf_(go) * tanhf(c);
            hd[r * HID + u] = dup2(h);
        }
    }
    __syncthreads();

    // ---- main GEMM: [64x64] @ [64x768] in 3 col passes of 256 ----
    const ull* hd = (const ull*)(sm + HD_OFF);
    float* wfA = (float*)(sm + WFA_OFF);
    float* wfB = (float*)(sm + WFB_OFF);

#pragma unroll 1
    for (int ct = 0; ct < 3; ct++) {
        int ctbase = ct * 256;
        // load W_fc tile (256 cols x 64 k), float4 LDG, scattered STS
        for (int i = t; i < 4096; i += 256) {
            int c = i >> 4, k4 = i & 15;
            float4 w = *(const float4*)(W_fc + (size_t)(ctbase + c) * HID + k4 * 4);
            int ccg = c >> 3, j = c & 7;
            float* dst = (j < 4) ? wfA : wfB;
            int jj = j & 3;
            dst[(4 * k4 + 0) * 132 + ccg * 4 + jj] = w.x;
            dst[(4 * k4 + 1) * 132 + ccg * 4 + jj] = w.y;
            dst[(4 * k4 + 2) * 132 + ccg * 4 + jj] = w.z;
            dst[(4 * k4 + 3) * 132 + ccg * 4 + jj] = w.w;
        }
        __syncthreads();

        ull acc[8][4];
        {
            ull bA0, bA1, bB0, bB1;
            ld2s(b_fc + ctbase + c0, bA0, bA1);
            ld2s(b_fc + ctbase + c0 + 4, bB0, bB1);
#pragma unroll
            for (int i = 0; i < 8; i++) {
                acc[i][0] = bA0; acc[i][1] = bA1; acc[i][2] = bB0; acc[i][3] = bB1;
            }
        }
#pragma unroll 8
        for (int k = 0; k < HID; k++) {
            ull w0, w1, w2, w3;
            ld2s(wfA + k * 132 + cg * 4, w0, w1);
            ld2s(wfB + k * 132 + cg * 4, w2, w3);
#pragma unroll
            for (int i = 0; i < 8; i++) {
                ull hv = hd[(r0 + i) * HID + k];
                ffma2(acc[i][0], hv, w0);
                ffma2(acc[i][1], hv, w1);
                ffma2(acc[i][2], hv, w2);
                ffma2(acc[i][3], hv, w3);
            }
        }
#pragma unroll
        for (int i = 0; i < 8; i++) {
            int row = row0 + r0 + i;
            if (row < N) {
                double2* dst = (double2*)(vs_out + (size_t)row * OUTF + ctbase + c0);
                dst[0] = make_double2(__longlong_as_double(acc[i][0]), __longlong_as_double(acc[i][1]));
                dst[1] = make_double2(__longlong_as_double(acc[i][2]), __longlong_as_double(acc[i][3]));
            }
        }
        __syncthreads();
    }
}

extern "C" void kernel_launch(void* const* d_in, const int* in_sizes, int n_in,
                              void* d_out, int out_size) {
    const float* VS     = (const float*)d_in[0];
    const float* CC     = (const float*)d_in[1];
    const int*   Level  = (const int*)d_in[2];
    const int*   Depart = (const int*)d_in[3];
    const float* W_ih   = (const float*)d_in[4];
    // d_in[5] = W_hh, unused (h0 = 0)
    const float* b_ih   = (const float*)d_in[6];
    const float* b_hh   = (const float*)d_in[7];
    const float* W_fc   = (const float*)d_in[8];
    const float* b_fc   = (const float*)d_in[9];

    int N = in_sizes[0] / NF;

    float* out = (float*)d_out;
    float* cc_out  = out;
    float* vs_out  = out + (size_t)N * OUTF;
    float* lev_out = out + (size_t)2 * N * OUTF;
    float* dep_out = lev_out + N;

    static int smem_set = 0;
    if (!smem_set) {
        cudaFuncSetAttribute(main_kernel,
                             cudaFuncAttributeMaxDynamicSharedMemorySize, SMEM_BYTES);
        smem_set = 1;
    }

    zero_kernel<<<(NBINS + 255) / 256, 256>>>();
    hist_kernel<<<256, 256>>>(VS, Level, N);
    prob_kernel<<<(NBINS + 255) / 256, 256>>>();
    main_kernel<<<(N + RB - 1) / RB, 256, SMEM_BYTES>>>(
        VS, Level, Depart, CC, W_ih, b_ih, b_hh, W_fc, b_fc,
        cc_out, vs_out, lev_out, dep_out, N);
}

// round 3
// speedup vs baseline: 1.1437x; 1.0909x over previous
#include <cuda_runtime.h>

#define NCLS 4
#define VMX 64
#define NF 28
#define HID 64
#define OUTF 768
#define NBINS (NCLS*VMX*NF)   // 7168
#define RBH 64                // rows per block, h_kernel
#define STRIP 256             // rows per gemm block (4 sub-blocks of 64)
#define NMAX 100096

typedef unsigned long long ull;

// static scratch (no allocations allowed)
__device__ int   g_counts[NBINS];
__device__ int   g_class[NCLS];
__device__ float g_prob[NBINS];
__device__ float g_h[(size_t)NMAX * HID];   // ~25.6 MB, stays L2-resident

// ---------------- prologue kernels ----------------
__global__ void zero_kernel() {
    int i = blockIdx.x * blockDim.x + threadIdx.x;
    if (i < NBINS) g_counts[i] = 0;
    if (i < NCLS)  g_class[i] = 0;
}

__global__ void hist_kernel(const float* __restrict__ VS,
                            const int* __restrict__ Level, int N) {
    __shared__ int s_counts[NBINS];
    __shared__ int s_cls[NCLS];
    for (int i = threadIdx.x; i < NBINS; i += blockDim.x) s_counts[i] = 0;
    if (threadIdx.x < NCLS) s_cls[threadIdx.x] = 0;
    __syncthreads();
    int stride = gridDim.x * blockDim.x;
    for (int r = blockIdx.x * blockDim.x + threadIdx.x; r < N; r += stride) {
        int lev = Level[r];
        atomicAdd(&s_cls[lev], 1);
        int base = lev * VMX;
#pragma unroll
        for (int c = 0; c < NF; c++) {
            int v = (int)VS[(size_t)r * NF + c];
            atomicAdd(&s_counts[(base + v) * NF + c], 1);
        }
    }
    __syncthreads();
    for (int i = threadIdx.x; i < NBINS; i += blockDim.x)
        if (s_counts[i]) atomicAdd(&g_counts[i], s_counts[i]);
    if (threadIdx.x < NCLS && s_cls[threadIdx.x])
        atomicAdd(&g_class[threadIdx.x], s_cls[threadIdx.x]);
}

__global__ void prob_kernel() {
    int i = blockIdx.x * blockDim.x + threadIdx.x;
    if (i < NBINS) {
        int cls = i / (VMX * NF);
        g_prob[i] = (float)g_counts[i] / (float)g_class[cls];
    }
}

// ---------------- helpers ----------------
__device__ __forceinline__ float sigmoidf_(float x) {
    return 1.0f / (1.0f + __expf(-x));
}
__device__ __forceinline__ ull dup2(float x) {
    ull p; asm("mov.b64 %0, {%1, %1};" : "=l"(p) : "f"(x)); return p;
}
__device__ __forceinline__ void ffma2(ull& d, ull a, ull b) {
    asm("fma.rn.f32x2 %0, %1, %2, %0;" : "+l"(d) : "l"(a), "l"(b));
}
__device__ __forceinline__ void ld2s(const float* p, ull& a, ull& b) {
    double2 d = *(const double2*)p;
    a = __double_as_longlong(d.x); b = __double_as_longlong(d.y);
}

// ---------------- h kernel: weighting + gates + activations ----------------
#define HK_SMEM (RBH*NF*4 + RBH*192*4)   // 7168 + 49152 = 56320

__global__ __launch_bounds__(256)
void h_kernel(const float* __restrict__ VS,
              const int* __restrict__ Level,
              const int* __restrict__ Depart,
              const float* __restrict__ W_ih,
              const float* __restrict__ b_ih,
              const float* __restrict__ b_hh,
              float* __restrict__ lev_out,
              float* __restrict__ dep_out,
              int N)
{
    extern __shared__ float hsm[];
    float* x_s = hsm;               // [64][28]
    float* g_s = hsm + RBH * NF;    // [64][192]  (i, g, o gates; f unused since c0=0)
    __shared__ int lev_s[RBH];

    const int t = threadIdx.x;
    const int row0 = blockIdx.x * RBH;

    if (t < RBH) {
        int r = row0 + t;
        int lv = (r < N) ? Level[r] : 0;
        lev_s[t] = lv;
        if (r < N) { lev_out[r] = (float)lv; dep_out[r] = (float)Depart[r]; }
    }
    __syncthreads();

    // x = VS * prob
    for (int i = t; i < RBH * NF; i += 256) {
        int r = i / NF, c = i % NF;
        float xv = 0.0f;
        if (row0 + r < N) {
            float v = VS[(size_t)(row0 + r) * NF + c];
            int lev = lev_s[r];
            xv = v * g_prob[(lev * VMX + (int)v) * NF + c];
        }
        x_s[r * NF + c] = xv;
    }
    __syncthreads();

    // gates for i,g,o only: thread t<192 owns gate column c
    if (t < 192) {
        int c = (t < 64) ? t : t + 64;     // skip f-gate block [64,128)
        float w[NF];
#pragma unroll
        for (int k = 0; k < NF; k++) w[k] = W_ih[c * NF + k];
        float b = b_ih[c] + b_hh[c];
#pragma unroll 4
        for (int r = 0; r < RBH; r++) {
            float acc = b;
#pragma unroll
            for (int k = 0; k < NF; k++) acc += w[k] * x_s[r * NF + k];
            g_s[r * 192 + t] = acc;
        }
    }
    __syncthreads();

    // activations -> g_h
    {
        int u = t & 63, rb = t >> 6;
#pragma unroll
        for (int m = 0; m < 16; m++) {
            int r = rb + 4 * m;
            float gi = g_s[r * 192 + u];
            float gg = g_s[r * 192 + 64 + u];
            float go = g_s[r * 192 + 128 + u];
            float c = sigmoidf_(gi) * tanhf(gg);
            float h = sigmoidf_(go) * tanhf(c);
            if (row0 + r < N) g_h[(size_t)(row0 + r) * HID + u] = h;
        }
    }
}

// ---------------- gemm kernel: h @ W_fc^T + b_fc, plus CC copy ----------------
// smem: wfA/wfB [64][132] floats each (swizzled), hd ull[64][64]
#define GEMM_SMEM (2*HID*132*4 + RBH*HID*8)   // 67584 + 32768 = 100352
#define SWZ(k) (((k) >> 2) & 31)

__global__ __launch_bounds__(256, 2)
void gemm_kernel(const float* __restrict__ CC,
                 const float* __restrict__ W_fc,
                 const float* __restrict__ b_fc,
                 float* __restrict__ cc_out,
                 float* __restrict__ vs_out,
                 int N)
{
    extern __shared__ char sm[];
    float* wfA = (float*)sm;
    float* wfB = wfA + HID * 132;
    ull*   hd  = (ull*)(sm + 2 * HID * 132 * 4);

    const int t  = threadIdx.x;
    const int cg = t & 31;        // col group: 8 cols
    const int rg = t >> 5;        // row group: 8 rows (== warp id)
    const int r0 = rg * 8;
    const int c0 = cg * 8;
    const int ct = blockIdx.y;
    const int ctbase = ct * 256;
    const int strip0 = blockIdx.x * STRIP;

    // ---- load W_fc col-group tile ONCE (swizzled layout) ----
    for (int i = t; i < 4096; i += 256) {
        int cl = i >> 4, k4 = i & 15;
        float4 w = *(const float4*)(W_fc + (size_t)(ctbase + cl) * HID + k4 * 4);
        int g = cl >> 3, j = cl & 7;
        float* buf = (j < 4) ? wfA : wfB;
        int jj = j & 3;
        float vals[4] = {w.x, w.y, w.z, w.w};
#pragma unroll
        for (int m = 0; m < 4; m++) {
            int k = 4 * k4 + m;
            buf[k * 132 + ((g ^ SWZ(k)) & 31) * 4 + jj] = vals[m];
        }
    }

    // ---- bias pairs ----
    ull bA0, bA1, bB0, bB1;
    ld2s(b_fc + ctbase + c0,     bA0, bA1);
    ld2s(b_fc + ctbase + c0 + 4, bB0, bB1);

#pragma unroll 1
    for (int s = 0; s < 4; s++) {
        int row0 = strip0 + s * 64;
        __syncthreads();   // hd reuse / W tile ready (s==0)

        // load h chunk -> duplicated f32x2
        for (int i = t; i < 4096; i += 256) {
            int r = i >> 6, k = i & 63;
            float hvf = (row0 + r < N) ? g_h[(size_t)(row0 + r) * HID + k] : 0.0f;
            hd[r * HID + k] = dup2(hvf);
        }
        // CC copy slice (this block's rows x this block's 256 cols)
        for (int i = t; i < 4096; i += 256) {
            int r = i >> 6, cv = i & 63;
            int row = row0 + r;
            if (row < N) {
                size_t off = (size_t)row * OUTF + ctbase + cv * 4;
                *(float4*)(cc_out + off) = *(const float4*)(CC + off);
            }
        }
        __syncthreads();

        // ---- 64x256 @ k=64 with 8x8 f32x2 register tiles ----
        ull acc[8][4];
#pragma unroll
        for (int i = 0; i < 8; i++) {
            acc[i][0] = bA0; acc[i][1] = bA1; acc[i][2] = bB0; acc[i][3] = bB1;
        }

        ull w0, w1, w2, w3;
        {
            int o = ((cg ^ SWZ(0)) & 31) * 4;
            ld2s(wfA + o, w0, w1);
            ld2s(wfB + o, w2, w3);
        }
#pragma unroll 4
        for (int k = 0; k < HID; k++) {
            ull nw0, nw1, nw2, nw3;
            if (k < HID - 1) {
                int kn = k + 1;
                int o = kn * 132 + ((cg ^ SWZ(kn)) & 31) * 4;
                ld2s(wfA + o, nw0, nw1);
                ld2s(wfB + o, nw2, nw3);
            }
#pragma unroll
            for (int i = 0; i < 8; i++) {
                ull hv = hd[(r0 + i) * HID + k];
                ffma2(acc[i][0], hv, w0);
                ffma2(acc[i][1], hv, w1);
                ffma2(acc[i][2], hv, w2);
                ffma2(acc[i][3], hv, w3);
            }
            if (k < HID - 1) { w0 = nw0; w1 = nw1; w2 = nw2; w3 = nw3; }
        }

#pragma unroll
        for (int i = 0; i < 8; i++) {
            int row = row0 + r0 + i;
            if (row < N) {
                double2* dst = (double2*)(vs_out + (size_t)row * OUTF + ctbase + c0);
                dst[0] = make_double2(__longlong_as_double(acc[i][0]),
                                      __longlong_as_double(acc[i][1]));
                dst[1] = make_double2(__longlong_as_double(acc[i][2]),
                                      __longlong_as_double(acc[i][3]));
            }
        }
    }
}

extern "C" void kernel_launch(void* const* d_in, const int* in_sizes, int n_in,
                              void* d_out, int out_size) {
    const float* VS     = (const float*)d_in[0];
    const float* CC     = (const float*)d_in[1];
    const int*   Level  = (const int*)d_in[2];
    const int*   Depart = (const int*)d_in[3];
    const float* W_ih   = (const float*)d_in[4];
    // d_in[5] = W_hh, unused (h0 = 0)
    const float* b_ih   = (const float*)d_in[6];
    const float* b_hh   = (const float*)d_in[7];
    const float* W_fc   = (const float*)d_in[8];
    const float* b_fc   = (const float*)d_in[9];

    int N = in_sizes[0] / NF;

    float* out = (float*)d_out;
    float* cc_out  = out;
    float* vs_out  = out + (size_t)N * OUTF;
    float* lev_out = out + (size_t)2 * N * OUTF;
    float* dep_out = lev_out + N;

    static int attr_set = 0;
    if (!attr_set) {
        cudaFuncSetAttribute(h_kernel,
                             cudaFuncAttributeMaxDynamicSharedMemorySize, HK_SMEM);
        cudaFuncSetAttribute(gemm_kernel,
                             cudaFuncAttributeMaxDynamicSharedMemorySize, GEMM_SMEM);
        attr_set = 1;
    }

    zero_kernel<<<(NBINS + 255) / 256, 256>>>();
    hist_kernel<<<256, 256>>>(VS, Level, N);
    prob_kernel<<<(NBINS + 255) / 256, 256>>>();
    h_kernel<<<(N + RBH - 1) / RBH, 256, HK_SMEM>>>(
        VS, Level, Depart, W_ih, b_ih, b_hh, lev_out, dep_out, N);
    dim3 ggrid((N + STRIP - 1) / STRIP, 3);
    gemm_kernel<<<ggrid, 256, GEMM_SMEM>>>(CC, W_fc, b_fc, cc_out, vs_out, N);
}

// round 4
// speedup vs baseline: 1.2340x; 1.0790x over previous
#include <cuda_runtime.h>

#define NCLS 4
#define VMX 64
#define NF 28
#define HID 64
#define OUTF 768
#define NBINS (NCLS*VMX*NF)   // 7168
#define RBH 64                // rows per block, h_kernel
#define STRIP 256             // rows per gemm block
#define NMAX 100096

typedef unsigned long long ull;

// static scratch (no allocations allowed)
__device__ int   g_counts[NBINS];
__device__ float g_prob[NBINS];
__device__ float g_h[(size_t)NMAX * HID];   // ~25.6 MB, stays L2-resident

// ---------------- prologue kernels ----------------
__global__ void zero_kernel() {
    int i = blockIdx.x * blockDim.x + threadIdx.x;
    if (i < NBINS) g_counts[i] = 0;
}

__global__ void hist_kernel(const float* __restrict__ VS,
                            const int* __restrict__ Level, int N) {
    __shared__ int s_counts[NBINS];
    for (int i = threadIdx.x; i < NBINS; i += blockDim.x) s_counts[i] = 0;
    __syncthreads();
    int stride = gridDim.x * blockDim.x;
    for (int r = blockIdx.x * blockDim.x + threadIdx.x; r < N; r += stride) {
        int lev = Level[r];
        int base = lev * VMX;
        const float4* vrow = (const float4*)(VS + (size_t)r * NF);
#pragma unroll
        for (int q = 0; q < 7; q++) {
            float4 v = vrow[q];
            atomicAdd(&s_counts[(base + (int)v.x) * NF + 4*q + 0], 1);
            atomicAdd(&s_counts[(base + (int)v.y) * NF + 4*q + 1], 1);
            atomicAdd(&s_counts[(base + (int)v.z) * NF + 4*q + 2], 1);
            atomicAdd(&s_counts[(base + (int)v.w) * NF + 4*q + 3], 1);
        }
    }
    __syncthreads();
    for (int i = threadIdx.x; i < NBINS; i += blockDim.x)
        if (s_counts[i]) atomicAdd(&g_counts[i], s_counts[i]);
}

// single block, 256 threads
__global__ void prob_kernel() {
    __shared__ float cls_sz[NCLS];
    int t = threadIdx.x;
    if (t < NCLS) cls_sz[t] = 0.0f;
    __syncthreads();
    // class size = sum over v of counts[(cls*64+v)*NF + 0]
    atomicAdd(&cls_sz[t >> 6], (float)g_counts[t * NF]);
    __syncthreads();
    for (int j = t; j < NBINS; j += 256) {
        int cls = j / (VMX * NF);
        g_prob[j] = (float)g_counts[j] / cls_sz[cls];
    }
}

// ---------------- helpers ----------------
__device__ __forceinline__ float sigmoidf_(float x) {
    return 1.0f / (1.0f + __expf(-x));
}
__device__ __forceinline__ ull dup2(float x) {
    ull p; asm("mov.b64 %0, {%1, %1};" : "=l"(p) : "f"(x)); return p;
}
__device__ __forceinline__ ull pack2(float lo, float hi) {
    ull p; asm("mov.b64 %0, {%1, %2};" : "=l"(p) : "f"(lo), "f"(hi)); return p;
}
__device__ __forceinline__ void unpack2(ull p, float& lo, float& hi) {
    asm("mov.b64 {%0, %1}, %2;" : "=f"(lo), "=f"(hi) : "l"(p));
}
__device__ __forceinline__ void ffma2(ull& d, ull a, ull b) {
    asm("fma.rn.f32x2 %0, %1, %2, %0;" : "+l"(d) : "l"(a), "l"(b));
}
__device__ __forceinline__ void ld2s(const float* p, ull& a, ull& b) {
    double2 d = *(const double2*)p;
    a = __double_as_longlong(d.x); b = __double_as_longlong(d.y);
}

// ---------------- h kernel: weighting + gates + activations ----------------
// row pairs packed as f32x2; gates for i,g,o only (f unused, c0=0)
#define HK_SMEM (32*NF*8 + 32*192*8)   // 7168 + 49152 = 56320

__global__ __launch_bounds__(256)
void h_kernel(const float* __restrict__ VS,
              const int* __restrict__ Level,
              const int* __restrict__ Depart,
              const float* __restrict__ W_ih,
              const float* __restrict__ b_ih,
              const float* __restrict__ b_hh,
              float* __restrict__ lev_out,
              float* __restrict__ dep_out,
              int N)
{
    extern __shared__ char hsm[];
    ull* x2 = (ull*)hsm;                 // [32 row-pairs][28]
    ull* g2 = (ull*)(hsm + 32*NF*8);     // [32 row-pairs][192]
    __shared__ int lev_s[RBH];

    const int t = threadIdx.x;
    const int row0 = blockIdx.x * RBH;

    if (t < RBH) {
        int r = row0 + t;
        int lv = (r < N) ? Level[r] : 0;
        lev_s[t] = lv;
        if (r < N) { lev_out[r] = (float)lv; dep_out[r] = (float)Depart[r]; }
    }
    __syncthreads();

    // x = VS * prob, packed as row pairs
    for (int i = t; i < RBH * NF; i += 256) {
        int r = i / NF, c = i % NF;
        float xv = 0.0f;
        if (row0 + r < N) {
            float v = VS[(size_t)(row0 + r) * NF + c];
            int lev = lev_s[r];
            xv = v * g_prob[(lev * VMX + (int)v) * NF + c];
        }
        ((float*)&x2[(r >> 1) * NF + c])[r & 1] = xv;
    }
    __syncthreads();

    // gates (i,g,o): thread t<192 owns gate index t -> real col c
    if (t < 192) {
        int c = (t < 64) ? t : t + 64;   // skip f-gate rows [64,128)
        ull wd[NF];
#pragma unroll
        for (int k = 0; k < NF; k++) wd[k] = dup2(W_ih[c * NF + k]);
        ull bd = dup2(b_ih[c] + b_hh[c]);
#pragma unroll 1
        for (int rp = 0; rp < 32; rp += 4) {
            ull a0 = bd, a1 = bd, a2 = bd, a3 = bd;
#pragma unroll
            for (int k = 0; k < NF; k++) {
                ffma2(a0, wd[k], x2[(rp + 0) * NF + k]);
                ffma2(a1, wd[k], x2[(rp + 1) * NF + k]);
                ffma2(a2, wd[k], x2[(rp + 2) * NF + k]);
                ffma2(a3, wd[k], x2[(rp + 3) * NF + k]);
            }
            g2[(rp + 0) * 192 + t] = a0;
            g2[(rp + 1) * 192 + t] = a1;
            g2[(rp + 2) * 192 + t] = a2;
            g2[(rp + 3) * 192 + t] = a3;
        }
    }
    __syncthreads();

    // activations -> g_h (two rows per pair)
    {
        int u = t & 63, ph = t >> 6;
#pragma unroll
        for (int m = 0; m < 8; m++) {
            int rp = ph * 8 + m;
            float gi0, gi1, gg0, gg1, go0, go1;
            unpack2(g2[rp * 192 + u], gi0, gi1);
            unpack2(g2[rp * 192 + 64 + u], gg0, gg1);
            unpack2(g2[rp * 192 + 128 + u], go0, go1);
            float c0v = sigmoidf_(gi0) * tanhf(gg0);
            float c1v = sigmoidf_(gi1) * tanhf(gg1);
            float h0 = sigmoidf_(go0) * tanhf(c0v);
            float h1 = sigmoidf_(go1) * tanhf(c1v);
            int r = row0 + 2 * rp;
            if (r < N)     g_h[(size_t)r * HID + u] = h0;
            if (r + 1 < N) g_h[(size_t)(r + 1) * HID + u] = h1;
        }
    }
}

// ---------------- gemm kernel: h @ W_fc^T + b_fc; copy blocks for CC ----------------
#define GEMM_SMEM (2*HID*132*4 + 64*HID*8)   // 67584 + 32768 = 100352
#define SWZ(k) (((k) >> 2) & 31)

__global__ __launch_bounds__(256, 2)
void gemm_kernel(const float* __restrict__ CC,
                 const float* __restrict__ W_fc,
                 const float* __restrict__ b_fc,
                 float* __restrict__ cc_out,
                 float* __restrict__ vs_out,
                 int N)
{
    extern __shared__ char sm[];
    float* wfA = (float*)sm;
    float* wfB = wfA + HID * 132;
    ull*   hd  = (ull*)(sm + 2 * HID * 132 * 4);

    const int t   = threadIdx.x;
    const int bid = blockIdx.x;
    const int strip0 = (bid >> 2) * STRIP;

    // ---- copy blocks: pure CC streaming (interleaved with gemm blocks) ----
    if ((bid & 3) == 3) {
        int nrow = (strip0 + STRIP <= N) ? STRIP : (N > strip0 ? N - strip0 : 0);
        int total = nrow * OUTF / 4;
        const float4* src = (const float4*)(CC + (size_t)strip0 * OUTF);
        float4* dst = (float4*)(cc_out + (size_t)strip0 * OUTF);
#pragma unroll 4
        for (int i = t; i < total; i += 256) dst[i] = src[i];
        return;
    }

    const int ct = bid & 3;              // 0..2
    const int ctbase = ct * 256;
    const int cg = t & 31;
    const int rg = t >> 5;
    const int r0 = rg * 8;
    const int c0 = cg * 8;

    // ---- load W_fc col-group tile ONCE (swizzled layout) ----
    for (int i = t; i < 4096; i += 256) {
        int cl = i >> 4, k4 = i & 15;
        float4 w = *(const float4*)(W_fc + (size_t)(ctbase + cl) * HID + k4 * 4);
        int g = cl >> 3, j = cl & 7;
        float* buf = (j < 4) ? wfA : wfB;
        int jj = j & 3;
        float vals[4] = {w.x, w.y, w.z, w.w};
#pragma unroll
        for (int m = 0; m < 4; m++) {
            int k = 4 * k4 + m;
            buf[k * 132 + ((g ^ SWZ(k)) & 31) * 4 + jj] = vals[m];
        }
    }

    ull bA0, bA1, bB0, bB1;
    ld2s(b_fc + ctbase + c0,     bA0, bA1);
    ld2s(b_fc + ctbase + c0 + 4, bB0, bB1);

#pragma unroll 1
    for (int s = 0; s < 4; s++) {
        int row0 = strip0 + s * 64;
        __syncthreads();   // hd safe to overwrite; W tile ready on s==0

        // load h chunk -> duplicated f32x2 (float4 LDG, 2x STS.128)
#pragma unroll
        for (int m = 0; m < 4; m++) {
            int idx = t + 256 * m;
            int r = idx >> 4, kq = idx & 15;
            float4 hv4 = make_float4(0.f, 0.f, 0.f, 0.f);
            if (row0 + r < N)
                hv4 = ((const float4*)(g_h + (size_t)(row0 + r) * HID))[kq];
            double2* p = (double2*)(hd + r * HID + kq * 4);
            p[0] = make_double2(__longlong_as_double(dup2(hv4.x)),
                                __longlong_as_double(dup2(hv4.y)));
            p[1] = make_double2(__longlong_as_double(dup2(hv4.z)),
                                __longlong_as_double(dup2(hv4.w)));
        }
        __syncthreads();

        // ---- 64x256 @ k=64, 8x8 f32x2 register tiles, k processed in pairs ----
        ull acc[8][4];
#pragma unroll
        for (int i = 0; i < 8; i++) {
            acc[i][0] = bA0; acc[i][1] = bA1; acc[i][2] = bB0; acc[i][3] = bB1;
        }

#pragma unroll 4
        for (int k2 = 0; k2 < HID / 2; k2++) {
            int ka = 2 * k2, kb = 2 * k2 + 1;
            int oa = ka * 132 + ((cg ^ SWZ(ka)) & 31) * 4;
            int ob = kb * 132 + ((cg ^ SWZ(kb)) & 31) * 4;
            ull w0, w1, w2, w3, v0, v1, v2, v3;
            ld2s(wfA + oa, w0, w1);
            ld2s(wfB + oa, w2, w3);
            ld2s(wfA + ob, v0, v1);
            ld2s(wfB + ob, v2, v3);
#pragma unroll
            for (int i = 0; i < 8; i++) {
                double2 hp = *(const double2*)(hd + (r0 + i) * HID + ka);
                ull ha = __double_as_longlong(hp.x);
                ull hb = __double_as_longlong(hp.y);
                ffma2(acc[i][0], ha, w0);
                ffma2(acc[i][1], ha, w1);
                ffma2(acc[i][2], ha, w2);
                ffma2(acc[i][3], ha, w3);
                ffma2(acc[i][0], hb, v0);
                ffma2(acc[i][1], hb, v1);
                ffma2(acc[i][2], hb, v2);
                ffma2(acc[i][3], hb, v3);
            }
        }

#pragma unroll
        for (int i = 0; i < 8; i++) {
            int row = row0 + r0 + i;
            if (row < N) {
                double2* dst = (double2*)(vs_out + (size_t)row * OUTF + ctbase + c0);
                dst[0] = make_double2(__longlong_as_double(acc[i][0]),
                                      __longlong_as_double(acc[i][1]));
                dst[1] = make_double2(__longlong_as_double(acc[i][2]),
                                      __longlong_as_double(acc[i][3]));
            }
        }
    }
}

extern "C" void kernel_launch(void* const* d_in, const int* in_sizes, int n_in,
                              void* d_out, int out_size) {
    const float* VS     = (const float*)d_in[0];
    const float* CC     = (const float*)d_in[1];
    const int*   Level  = (const int*)d_in[2];
    const int*   Depart = (const int*)d_in[3];
    const float* W_ih   = (const float*)d_in[4];
    // d_in[5] = W_hh, unused (h0 = 0)
    const float* b_ih   = (const float*)d_in[6];
    const float* b_hh   = (const float*)d_in[7];
    const float* W_fc   = (const float*)d_in[8];
    const float* b_fc   = (const float*)d_in[9];

    int N = in_sizes[0] / NF;

    float* out = (float*)d_out;
    float* cc_out  = out;
    float* vs_out  = out + (size_t)N * OUTF;
    float* lev_out = out + (size_t)2 * N * OUTF;
    float* dep_out = lev_out + N;

    static int attr_set = 0;
    if (!attr_set) {
        cudaFuncSetAttribute(h_kernel,
                             cudaFuncAttributeMaxDynamicSharedMemorySize, HK_SMEM);
        cudaFuncSetAttribute(gemm_kernel,
                             cudaFuncAttributeMaxDynamicSharedMemorySize, GEMM_SMEM);
        attr_set = 1;
    }

    zero_kernel<<<(NBINS + 255) / 256, 256>>>();
    hist_kernel<<<148, 256>>>(VS, Level, N);
    prob_kernel<<<1, 256>>>();
    h_kernel<<<(N + RBH - 1) / RBH, 256, HK_SMEM>>>(
        VS, Level, Depart, W_ih, b_ih, b_hh, lev_out, dep_out, N);
    int nstrip = (N + STRIP - 1) / STRIP;
    gemm_kernel<<<nstrip * 4, 256, GEMM_SMEM>>>(CC, W_fc, b_fc, cc_out, vs_out, N);
}

// round 6
// speedup vs baseline: 1.6397x; 1.3287x over previous
#include <cuda_runtime.h>
#include <cuda_bf16.h>
#include <cstdint>

#define NCLS 4
#define VMX 64
#define NF 28
#define HID 64
#define OUTF 768
#define NBINS (NCLS*VMX*NF)   // 7168
#define RBH 64
#define NMAX 100096
#define MTILE 128
#define NTILE 128

typedef unsigned long long ull;

// static scratch (no allocations allowed)
__device__ int   g_counts[NBINS];
__device__ float g_prob[NBINS];
__device__ __align__(16) __nv_bfloat16 g_hh[(size_t)NMAX * HID];
__device__ __align__(16) __nv_bfloat16 g_hl[(size_t)NMAX * HID];
__device__ __align__(16) __nv_bfloat16 g_wh[OUTF * HID];
__device__ __align__(16) __nv_bfloat16 g_wl[OUTF * HID];

// ---------------- prologue kernels ----------------
__global__ void zero_kernel() {
    int i = blockIdx.x * blockDim.x + threadIdx.x;
    if (i < NBINS) g_counts[i] = 0;
}

__global__ void hist_kernel(const float* __restrict__ VS,
                            const int* __restrict__ Level, int N) {
    __shared__ int s_counts[NBINS];
    for (int i = threadIdx.x; i < NBINS; i += blockDim.x) s_counts[i] = 0;
    __syncthreads();
    int stride = gridDim.x * blockDim.x;
    for (int r = blockIdx.x * blockDim.x + threadIdx.x; r < N; r += stride) {
        int lev = Level[r];
        int base = lev * VMX;
        const float4* vrow = (const float4*)(VS + (size_t)r * NF);
#pragma unroll
        for (int q = 0; q < 7; q++) {
            float4 v = vrow[q];
            atomicAdd(&s_counts[(base + (int)v.x) * NF + 4*q + 0], 1);
            atomicAdd(&s_counts[(base + (int)v.y) * NF + 4*q + 1], 1);
            atomicAdd(&s_counts[(base + (int)v.z) * NF + 4*q + 2], 1);
            atomicAdd(&s_counts[(base + (int)v.w) * NF + 4*q + 3], 1);
        }
    }
    __syncthreads();
    for (int i = threadIdx.x; i < NBINS; i += blockDim.x)
        if (s_counts[i]) atomicAdd(&g_counts[i], s_counts[i]);
}

__global__ void prob_kernel() {
    __shared__ float cls_sz[NCLS];
    int t = threadIdx.x;
    if (t < NCLS) cls_sz[t] = 0.0f;
    __syncthreads();
    atomicAdd(&cls_sz[t >> 6], (float)g_counts[t * NF]);
    __syncthreads();
    for (int j = t; j < NBINS; j += 256) {
        int cls = j / (VMX * NF);
        g_prob[j] = (float)g_counts[j] / cls_sz[cls];
    }
}

__global__ void wconv_kernel(const float* __restrict__ W) {
    int i = blockIdx.x * blockDim.x + threadIdx.x;
    if (i < OUTF * HID) {
        float w = W[i];
        __nv_bfloat16 hi = __float2bfloat16(w);
        g_wh[i] = hi;
        g_wl[i] = __float2bfloat16(w - __bfloat162float(hi));
    }
}

// ---------------- helpers ----------------
__device__ __forceinline__ float sigmoidf_(float x) {
    return 1.0f / (1.0f + __expf(-x));
}
__device__ __forceinline__ ull dup2(float x) {
    ull p; asm("mov.b64 %0, {%1, %1};" : "=l"(p) : "f"(x)); return p;
}
__device__ __forceinline__ void unpack2(ull p, float& lo, float& hi) {
    asm("mov.b64 {%0, %1}, %2;" : "=f"(lo), "=f"(hi) : "l"(p));
}
__device__ __forceinline__ void ffma2(ull& d, ull a, ull b) {
    asm("fma.rn.f32x2 %0, %1, %2, %0;" : "+l"(d) : "l"(a), "l"(b));
}
__device__ __forceinline__ uint32_t smem_u32(const void* p) {
    uint32_t a;
    asm("{ .reg .u64 t; cvta.to.shared.u64 t, %1; cvt.u32.u64 %0, t; }"
        : "=r"(a) : "l"(p));
    return a;
}
__device__ __forceinline__ void ldsm4(uint32_t addr, uint32_t* r) {
    asm volatile("ldmatrix.sync.aligned.m8n8.x4.shared.b16 {%0,%1,%2,%3}, [%4];"
        : "=r"(r[0]), "=r"(r[1]), "=r"(r[2]), "=r"(r[3]) : "r"(addr));
}
__device__ __forceinline__ void mma_bf16(float* c, const uint32_t* a,
                                         uint32_t b0, uint32_t b1) {
    asm volatile(
        "mma.sync.aligned.m16n8k16.row.col.f32.bf16.bf16.f32 "
        "{%0,%1,%2,%3}, {%4,%5,%6,%7}, {%8,%9}, {%0,%1,%2,%3};"
        : "+f"(c[0]), "+f"(c[1]), "+f"(c[2]), "+f"(c[3])
        : "r"(a[0]), "r"(a[1]), "r"(a[2]), "r"(a[3]), "r"(b0), "r"(b1));
}

// ---------------- h kernel ----------------
#define HK_SMEM (32*NF*8 + 32*192*8)   // 56320

__global__ __launch_bounds__(256)
void h_kernel(const float* __restrict__ VS,
              const int* __restrict__ Level,
              const int* __restrict__ Depart,
              const float* __restrict__ W_ih,
              const float* __restrict__ b_ih,
              const float* __restrict__ b_hh,
              float* __restrict__ lev_out,
              float* __restrict__ dep_out,
              int N)
{
    extern __shared__ char hsm[];
    ull* x2 = (ull*)hsm;                 // [32 row-pairs][28]
    ull* g2 = (ull*)(hsm + 32*NF*8);     // [32 row-pairs][192]
    __shared__ int lev_s[RBH];

    const int t = threadIdx.x;
    const int row0 = blockIdx.x * RBH;

    if (t < RBH) {
        int r = row0 + t;
        int lv = (r < N) ? Level[r] : 0;
        lev_s[t] = lv;
        if (r < N) { lev_out[r] = (float)lv; dep_out[r] = (float)Depart[r]; }
    }
    __syncthreads();

    for (int i = t; i < RBH * NF; i += 256) {
        int r = i / NF, c = i % NF;
        float xv = 0.0f;
        if (row0 + r < N) {
            float v = VS[(size_t)(row0 + r) * NF + c];
            int lev = lev_s[r];
            xv = v * g_prob[(lev * VMX + (int)v) * NF + c];
        }
        ((float*)&x2[(r >> 1) * NF + c])[r & 1] = xv;
    }
    __syncthreads();

    if (t < 192) {
        int c = (t < 64) ? t : t + 64;   // skip f-gate block (c0 = 0)
        ull wd[NF];
#pragma unroll
        for (int k = 0; k < NF; k++) wd[k] = dup2(W_ih[c * NF + k]);
        ull bd = dup2(b_ih[c] + b_hh[c]);
#pragma unroll 1
        for (int rp = 0; rp < 32; rp += 4) {
            ull a0 = bd, a1 = bd, a2 = bd, a3 = bd;
#pragma unroll
            for (int k = 0; k < NF; k++) {
                ffma2(a0, wd[k], x2[(rp + 0) * NF + k]);
                ffma2(a1, wd[k], x2[(rp + 1) * NF + k]);
                ffma2(a2, wd[k], x2[(rp + 2) * NF + k]);
                ffma2(a3, wd[k], x2[(rp + 3) * NF + k]);
            }
            g2[(rp + 0) * 192 + t] = a0;
            g2[(rp + 1) * 192 + t] = a1;
            g2[(rp + 2) * 192 + t] = a2;
            g2[(rp + 3) * 192 + t] = a3;
        }
    }
    __syncthreads();

    {
        int u = t & 63, ph = t >> 6;
#pragma unroll
        for (int m = 0; m < 8; m++) {
            int rp = ph * 8 + m;
            float gi0, gi1, gg0, gg1, go0, go1;
            unpack2(g2[rp * 192 + u], gi0, gi1);
            unpack2(g2[rp * 192 + 64 + u], gg0, gg1);
            unpack2(g2[rp * 192 + 128 + u], go0, go1);
            float c0v = sigmoidf_(gi0) * tanhf(gg0);
            float c1v = sigmoidf_(gi1) * tanhf(gg1);
            float h0 = sigmoidf_(go0) * tanhf(c0v);
            float h1 = sigmoidf_(go1) * tanhf(c1v);
            int r = row0 + 2 * rp;
            if (r < N) {
                __nv_bfloat16 hi = __float2bfloat16(h0);
                g_hh[(size_t)r * HID + u] = hi;
                g_hl[(size_t)r * HID + u] = __float2bfloat16(h0 - __bfloat162float(hi));
            }
            if (r + 1 < N) {
                __nv_bfloat16 hi = __float2bfloat16(h1);
                g_hh[(size_t)(r + 1) * HID + u] = hi;
                g_hl[(size_t)(r + 1) * HID + u] = __float2bfloat16(h1 - __bfloat162float(hi));
            }
        }
    }
}

// ---------------- gemm kernel: mma.sync bf16 3-term split + CC copy ----------------
// smem layout: rows stored with 48B stride (24 halves) for conflict-free ldmatrix
// A_s[term][kc(4)][r(128)][24h] ; B_s same with n(128)
#define A_HI 0
#define A_LO 24576
#define B_HI 49152
#define B_LO 73728
#define S_BIAS 98304
#define GEMM_SMEM 98816
#define KCB 6144    // bytes per kc block (128*48)

__global__ __launch_bounds__(256, 2)
void gemm_kernel(const float* __restrict__ CC,
                 const float* __restrict__ b_fc,
                 float* __restrict__ cc_out,
                 float* __restrict__ vs_out,
                 int N)
{
    extern __shared__ char sm[];
    const int t = threadIdx.x;
    const int lane = t & 31;
    const int wm = t >> 5;            // warp id -> 16-row group
    const int row0 = blockIdx.x * MTILE;
    const int ctb  = blockIdx.y * NTILE;
    const uint32_t sb = smem_u32(sm);

    // bias
    if (t < 32) ((float4*)(sm + S_BIAS))[t] = ((const float4*)(b_fc + ctb))[t];

    // A fill (hi/lo): per (r, q): q = 16B chunk index 0..7 -> kc = q>>1, half = q&1
#pragma unroll
    for (int j = 0; j < 4; j++) {
        int i = t + j * 256;
        int r = i >> 3, q = i & 7;
        int kc = q >> 1, hf = q & 1;
        uint4 vh = make_uint4(0, 0, 0, 0), vl = make_uint4(0, 0, 0, 0);
        if (row0 + r < N) {
            vh = ((const uint4*)(g_hh + (size_t)(row0 + r) * HID))[q];
            vl = ((const uint4*)(g_hl + (size_t)(row0 + r) * HID))[q];
        }
        *(uint4*)(sm + A_HI + kc * KCB + r * 48 + hf * 16) = vh;
        *(uint4*)(sm + A_LO + kc * KCB + r * 48 + hf * 16) = vl;
    }
    // B fill (hi/lo)
#pragma unroll
    for (int j = 0; j < 4; j++) {
        int i = t + j * 256;
        int n = i >> 3, q = i & 7;
        int kc = q >> 1, hf = q & 1;
        *(uint4*)(sm + B_HI + kc * KCB + n * 48 + hf * 16) =
            ((const uint4*)(g_wh + (size_t)(ctb + n) * HID))[q];
        *(uint4*)(sm + B_LO + kc * KCB + n * 48 + hf * 16) =
            ((const uint4*)(g_wl + (size_t)(ctb + n) * HID))[q];
    }
    __syncthreads();

    // CC copy (128 rows x 128 cols) — DRAM work overlapping the MMA phase
#pragma unroll 4
    for (int j = 0; j < 16; j++) {
        int i = t + j * 256;
        int r = i >> 5, c4 = i & 31;
        int row = row0 + r;
        if (row < N) {
            size_t off = (size_t)row * OUTF + ctb + c4 * 4;
            *(float4*)(cc_out + off) = *(const float4*)(CC + off);
        }
    }

    // accumulators: 16 n-tiles x 4 regs, init with bias
    float acc[16][4];
    {
        const float* bs = (const float*)(sm + S_BIAS);
        int cb = (lane & 3) * 2;
#pragma unroll
        for (int nt = 0; nt < 16; nt++) {
            float b0 = bs[nt * 8 + cb], b1 = bs[nt * 8 + cb + 1];
            acc[nt][0] = b0; acc[nt][1] = b1; acc[nt][2] = b0; acc[nt][3] = b1;
        }
    }

    const int rowb = wm * 16;
    // ldmatrix lane addressing
    const uint32_t a_lane_off = (uint32_t)((rowb + (lane & 15)) * 48 + ((lane & 16) ? 16 : 0));
    const uint32_t b_row_off  = (uint32_t)((lane & 7) * 48 + ((lane & 8) ? 16 : 0));
    const uint32_t b_kc_sel   = (uint32_t)(((lane >> 4) & 1) * KCB);

#pragma unroll
    for (int p = 0; p < 2; p++) {
        uint32_t Ah[2][4], Al[2][4];
#pragma unroll
        for (int j = 0; j < 2; j++) {
            int kc = 2 * p + j;
            ldsm4(sb + A_HI + kc * KCB + a_lane_off, Ah[j]);
            ldsm4(sb + A_LO + kc * KCB + a_lane_off, Al[j]);
        }
#pragma unroll
        for (int nt = 0; nt < 16; nt++) {
            uint32_t Bh[4], Bl[4];
            uint32_t boff = 2 * p * KCB + b_kc_sel + (uint32_t)(nt * 8 * 48) + b_row_off;
            ldsm4(sb + B_HI + boff, Bh);
            ldsm4(sb + B_LO + boff, Bl);
#pragma unroll
            for (int j = 0; j < 2; j++) {
                mma_bf16(acc[nt], Ah[j], Bh[2 * j], Bh[2 * j + 1]);
                mma_bf16(acc[nt], Ah[j], Bl[2 * j], Bl[2 * j + 1]);
                mma_bf16(acc[nt], Al[j], Bh[2 * j], Bh[2 * j + 1]);
            }
        }
    }

    // epilogue: direct STG.64 (each 4-lane group writes a full 32B sector)
    {
        int r_lo = row0 + rowb + (lane >> 2);
        int r_hi = r_lo + 8;
        int cb = ctb + (lane & 3) * 2;
#pragma unroll
        for (int nt = 0; nt < 16; nt++) {
            if (r_lo < N) {
                float2 v = make_float2(acc[nt][0], acc[nt][1]);
                *(float2*)(vs_out + (size_t)r_lo * OUTF + cb + nt * 8) = v;
            }
            if (r_hi < N) {
                float2 v = make_float2(acc[nt][2], acc[nt][3]);
                *(float2*)(vs_out + (size_t)r_hi * OUTF + cb + nt * 8) = v;
            }
        }
    }
}

extern "C" void kernel_launch(void* const* d_in, const int* in_sizes, int n_in,
                              void* d_out, int out_size) {
    const float* VS     = (const float*)d_in[0];
    const float* CC     = (const float*)d_in[1];
    const int*   Level  = (const int*)d_in[2];
    const int*   Depart = (const int*)d_in[3];
    const float* W_ih   = (const float*)d_in[4];
    // d_in[5] = W_hh, unused (h0 = 0)
    const float* b_ih   = (const float*)d_in[6];
    const float* b_hh   = (const float*)d_in[7];
    const float* W_fc   = (const float*)d_in[8];
    const float* b_fc   = (const float*)d_in[9];

    int N = in_sizes[0] / NF;

    float* out = (float*)d_out;
    float* cc_out  = out;
    float* vs_out  = out + (size_t)N * OUTF;
    float* lev_out = out + (size_t)2 * N * OUTF;
    float* dep_out = lev_out + N;

    static int attr_set = 0;
    if (!attr_set) {
        cudaFuncSetAttribute(h_kernel,
                             cudaFuncAttributeMaxDynamicSharedMemorySize, HK_SMEM);
        cudaFuncSetAttribute(gemm_kernel,
                             cudaFuncAttributeMaxDynamicSharedMemorySize, GEMM_SMEM);
        attr_set = 1;
    }

    zero_kernel<<<(NBINS + 255) / 256, 256>>>();
    hist_kernel<<<148, 256>>>(VS, Level, N);
    prob_kernel<<<1, 256>>>();
    wconv_kernel<<<(OUTF * HID + 255) / 256, 256>>>(W_fc);
    h_kernel<<<(N + RBH - 1) / RBH, 256, HK_SMEM>>>(
        VS, Level, Depart, W_ih, b_ih, b_hh, lev_out, dep_out, N);
    dim3 ggrid((N + MTILE - 1) / MTILE, OUTF / NTILE);
    gemm_kernel<<<ggrid, 256, GEMM_SMEM>>>(CC, b_fc, cc_out, vs_out, N);
}